// round 10
// baseline (speedup 1.0000x reference)
#include <cuda_runtime.h>
#include <cstdint>
#include <cstddef>

namespace {

constexpr int kB  = 4;
constexpr int kH  = 8;
constexpr int kL  = 2048;
constexpr int kR  = 8;
constexpr int kDV = 128;

constexpr int TM = 64;           // rows per CTA
constexpr int KT = 32;           // K-tile
constexpr int NT = 256;          // threads
constexpr int NTILES = kL / KT;  // 64
constexpr int A2C   = 256;       // a2 chunk cols (phase 1)
constexpr int NCHUNK = kL / A2C; // 8

constexpr int PSTRIDE = 36;      // p row stride (u32): A-frag conflict-free
constexpr int VSTRIDE = 136;     // v row stride (u32): B-frag conflict-free
constexpr float kLog2e = 1.44269504088896340736f;

typedef unsigned long long ull;

__device__ __forceinline__ ull dup2(float x) {
    ull r; asm("mov.b64 %0, {%1,%1};" : "=l"(r) : "f"(x)); return r;
}
__device__ __forceinline__ void unpack2(ull v, float& lo, float& hi) {
    asm("mov.b64 {%0,%1}, %2;" : "=f"(lo), "=f"(hi) : "l"(v));
}
__device__ __forceinline__ ull fma2(ull a, ull b, ull c) {
    ull d; asm("fma.rn.f32x2 %0, %1, %2, %3;" : "=l"(d) : "l"(a), "l"(b), "l"(c));
    return d;
}
__device__ __forceinline__ uint32_t f2tf32(float x) {
    uint32_t r; asm("cvt.rna.tf32.f32 %0, %1;" : "=r"(r) : "f"(x)); return r;
}
__device__ __forceinline__ float ex2(float x) {
    float r; asm("ex2.approx.f32 %0, %1;" : "=f"(r) : "f"(x)); return r;
}
__device__ __forceinline__ float lg2(float x) {
    float r; asm("lg2.approx.f32 %0, %1;" : "=f"(r) : "f"(x)); return r;
}
__device__ __forceinline__ void mma_tf32(float d[4], const uint32_t a[4],
                                         uint32_t b0, uint32_t b1) {
    asm volatile(
        "mma.sync.aligned.m16n8k8.row.col.f32.tf32.tf32.f32 "
        "{%0,%1,%2,%3}, {%4,%5,%6,%7}, {%8,%9}, {%0,%1,%2,%3};"
        : "+f"(d[0]), "+f"(d[1]), "+f"(d[2]), "+f"(d[3])
        : "r"(a[0]), "r"(a[1]), "r"(a[2]), "r"(a[3]), "r"(b0), "r"(b1));
}
__device__ __forceinline__ uint32_t smem_u32(const void* p) {
    uint32_t a;
    asm("{ .reg .u64 t; cvta.to.shared.u64 t, %1; cvt.u32.u64 %0, t; }"
        : "=r"(a) : "l"(p));
    return a;
}
__device__ __forceinline__ void cp16(uint32_t saddr, const void* g) {
    asm volatile("cp.async.ca.shared.global [%0], [%1], 16;"
                 :: "r"(saddr), "l"(g) : "memory");
}
__device__ __forceinline__ void cp_commit() {
    asm volatile("cp.async.commit_group;" ::: "memory");
}
__device__ __forceinline__ void cp_wait1() {
    asm volatile("cp.async.wait_group 1;" ::: "memory");
}
__device__ __forceinline__ void cp_wait0() {
    asm volatile("cp.async.wait_group 0;" ::: "memory");
}

struct __align__(16) SmemLayout {
    uint32_t p[2][TM][PSTRIDE];    // 18.4 KB (tf32 normalized-E tiles, double buffered)
    uint32_t v[3][KT][VSTRIDE];    // 52.2 KB (raw f32 v tiles, cp.async ring)
    float    a2t[2][kR][KT];       // 2 KB   (phase-2 streamed a2 K-tiles)
    float    a2c[3][kR][A2C];      // 24.6 KB (phase-1 a2 chunk ring)
};
// ~95 KB -> 2 CTAs/SM

__global__ void __launch_bounds__(NT, 2)
fra_kernel(const float* __restrict__ gv,
           const float* __restrict__ ga1,
           const float* __restrict__ ga2,
           const int*   __restrict__ gmask,
           float* __restrict__ gout,
           float* __restrict__ gattn)
{
    extern __shared__ char smem_raw[];
    SmemLayout& S = *reinterpret_cast<SmemLayout*>(smem_raw);

    const int h    = blockIdx.x;   // heads fastest: 8 heads share mask tile in L2
    const int tile = blockIdx.y;
    const int b    = blockIdx.z;
    const int bh   = b * kH + h;
    const int i0g  = tile * TM;
    const int t    = threadIdx.x;
    const int w    = t >> 5;
    const int l    = t & 31;

    const float* a2base = ga2 + (size_t)bh * kR * kL;
    const float* a1base = ga1 + ((size_t)bh * kL + i0g) * kR;
    const float* vbase  = gv  + (size_t)bh * kL * kDV;
    const int*   mbase  = gmask + ((size_t)b * kL + i0g) * kL;
    float* attnbase = gattn + ((size_t)bh * kL + i0g) * kL;
    float* outbase  = gout  + ((size_t)bh * kL + i0g) * kDV;

    // score mapping: rows 2*rp+i (i=0,1), cols cg*4 within K-tile
    const int rp = t >> 3;   // 0..31
    const int cg = t & 7;    // 0..7

    // a1 (pre-scaled by log2e) for this thread's 2 rows
    float a1r[2][kR];
    #pragma unroll
    for (int i = 0; i < 2; ++i) {
        const float4* src = (const float4*)(a1base + (size_t)(rp * 2 + i) * kR);
        float4 q0 = src[0], q1 = src[1];
        a1r[i][0] = q0.x * kLog2e; a1r[i][1] = q0.y * kLog2e;
        a1r[i][2] = q0.z * kLog2e; a1r[i][3] = q0.w * kLog2e;
        a1r[i][4] = q1.x * kLog2e; a1r[i][5] = q1.y * kLog2e;
        a1r[i][6] = q1.z * kLog2e; a1r[i][7] = q1.w * kLog2e;
    }

    // =================== Phase 1: rowsums (no stores) ===================
    float l2i[2];
    {
        const uint32_t a2c_base = smem_u32(&S.a2c[0][0][0]);
        constexpr uint32_t A2C_SLOT = kR * A2C * 4;   // 8 KB
        const int cr0 = t >> 6;            // 0..3
        const int cc0 = (t & 63) * 4;      // float col
        const uint32_t coff0 = (uint32_t)((cr0 * A2C + cc0) * 4);
        const uint32_t coff1 = (uint32_t)(((cr0 + 4) * A2C + cc0) * 4);
        const float* cga = a2base + (size_t)cr0 * kL + cc0;
        const float* cgb = a2base + (size_t)(cr0 + 4) * kL + cc0;

        // chunk 0 -> slot 0
        cp16(a2c_base + coff0, cga);
        cp16(a2c_base + coff1, cgb);
        cp_commit();

        // preload mask subtile 0
        int4 pm[2];
        pm[0] = *(const int4*)(mbase + (size_t)(rp * 2 + 0) * kL + cg * 4);
        pm[1] = *(const int4*)(mbase + (size_t)(rp * 2 + 1) * kL + cg * 4);

        float rs[2] = {0.f, 0.f};
        int cslot = 0, cnxt = 1;
        for (int c = 0; c < NCHUNK; ++c) {
            if (c + 1 < NCHUNK) {
                const uint32_t sb = a2c_base + (uint32_t)cnxt * A2C_SLOT;
                cp16(sb + coff0, cga + (c + 1) * A2C);
                cp16(sb + coff1, cgb + (c + 1) * A2C);
                cp_commit();
                cp_wait1();
            } else {
                cp_wait0();
            }
            __syncthreads();   // slot cslot resident; ring distance 3 protects writes

            const float* a2cp = &S.a2c[cslot][0][0];
            #pragma unroll
            for (int k = 0; k < 8; ++k) {
                ull sac[2][2];
                sac[0][0] = 0ULL; sac[0][1] = 0ULL;
                sac[1][0] = 0ULL; sac[1][1] = 0ULL;
                #pragma unroll
                for (int r = 0; r < kR; ++r) {
                    ulonglong2 q =
                        *(const ulonglong2*)(a2cp + (size_t)r * A2C + k * KT + cg * 4);
                    #pragma unroll
                    for (int i = 0; i < 2; ++i) {
                        ull ad = dup2(a1r[i][r]);
                        sac[i][0] = fma2(ad, q.x, sac[i][0]);
                        sac[i][1] = fma2(ad, q.y, sac[i][1]);
                    }
                }
                // preload next subtile's mask
                const int stn = c * 8 + k + 1;
                const int jn  = (stn < NTILES) ? stn * KT : 0;
                int4 nm0 = *(const int4*)(mbase + (size_t)(rp * 2 + 0) * kL + jn + cg * 4);
                int4 nm1 = *(const int4*)(mbase + (size_t)(rp * 2 + 1) * kL + jn + cg * 4);
                #pragma unroll
                for (int i = 0; i < 2; ++i) {
                    float e0, e1, e2, e3;
                    unpack2(sac[i][0], e0, e1);
                    unpack2(sac[i][1], e2, e3);
                    const int4 m = pm[i];
                    float s01 = (m.x ? ex2(e0) : 0.f) + (m.y ? ex2(e1) : 0.f);
                    float s23 = (m.z ? ex2(e2) : 0.f) + (m.w ? ex2(e3) : 0.f);
                    rs[i] += s01 + s23;
                }
                pm[0] = nm0; pm[1] = nm1;
            }
            cslot = cnxt;
            cnxt = (cnxt == 2) ? 0 : cnxt + 1;
        }

        // reduce over the 8 cg lanes sharing each row (warp-local)
        #pragma unroll
        for (int i = 0; i < 2; ++i) {
            float r = rs[i];
            r += __shfl_xor_sync(0xffffffffu, r, 1);
            r += __shfl_xor_sync(0xffffffffu, r, 2);
            r += __shfl_xor_sync(0xffffffffu, r, 4);
            l2i[i] = -lg2(r);      // fold 1/rowsum into the exponent
        }
    }

    const ull l2id[2] = { dup2(l2i[0]), dup2(l2i[1]) };

    // GEMM warp grid 2x4 (wm x wn); warp tile 32 rows x 32 cols
    const int wm  = w >> 2;
    const int wn  = w & 3;
    const int qid = l >> 2;
    const int tig = l & 3;

    float acc[2][4][4];
    #pragma unroll
    for (int mt = 0; mt < 2; ++mt)
        #pragma unroll
        for (int nt = 0; nt < 4; ++nt)
            #pragma unroll
            for (int e = 0; e < 4; ++e) acc[mt][nt][e] = 0.f;

    // ---- cp.async v addressing ----
    const uint32_t vs_base = smem_u32(&S.v[0][0][0]);
    uint32_t voff[4];
    #pragma unroll
    for (int k = 0; k < 4; ++k)
        voff[k] = (uint32_t)(((w + 8 * k) * VSTRIDE + 4 * l) * 4);
    const float* vg[4];
    #pragma unroll
    for (int k = 0; k < 4; ++k)
        vg[k] = vbase + (size_t)(w + 8 * k) * kDV + 4 * l;
    constexpr uint32_t VSLOT = KT * VSTRIDE * 4;
    constexpr size_t   VGT   = (size_t)KT * kDV;

    // ---- phase-2 prologue ----
    #pragma unroll
    for (int k = 0; k < 4; ++k) cp16(vs_base + voff[k], vg[k]);
    cp_commit();

    const int ar = t >> 3;
    const int ac = t & 7;
    if (t < 64)
        *(float4*)&S.a2t[0][ar][ac * 4] =
            *(const float4*)(a2base + (size_t)ar * kL + ac * 4);

    int4 mq_buf[2][2];
    #pragma unroll
    for (int i = 0; i < 2; ++i) {
        mq_buf[0][i] = *(const int4*)(mbase + (size_t)(rp * 2 + i) * kL + 0 * KT + cg * 4);
        mq_buf[1][i] = *(const int4*)(mbase + (size_t)(rp * 2 + i) * kL + 1 * KT + cg * 4);
    }
    __syncthreads();

    // ============ Phase 2: normalized e = mask*exp2(s+l2i); attn STG; E@V MMA ============
    int vcur = 0, vnxt = 1;
    #pragma unroll 2
    for (int jt = 0; jt < NTILES; ++jt) {
        const int buf = jt & 1;
        const int j0  = jt * KT;

        // ---- issue cp.async for v tile jt+1 ----
        {
            const size_t goff = (jt + 1 < NTILES) ? (size_t)(jt + 1) * VGT : 0;
            const uint32_t sb = vs_base + (uint32_t)vnxt * VSLOT;
            #pragma unroll
            for (int k = 0; k < 4; ++k) cp16(sb + voff[k], vg[k] + goff);
            cp_commit();
        }

        // ---- prefetch next a2 tile ----
        float4 a2n;
        const int jn = (jt + 1 < NTILES) ? j0 + KT : 0;
        if (t < 64)
            a2n = *(const float4*)(a2base + (size_t)ar * kL + jn + ac * 4);

        // ---- scores (accumulator pre-seeded with -log2(rowsum)) ----
        ull sac[2][2];
        sac[0][0] = l2id[0]; sac[0][1] = l2id[0];
        sac[1][0] = l2id[1]; sac[1][1] = l2id[1];
        #pragma unroll
        for (int r = 0; r < kR; ++r) {
            ulonglong2 q = *(const ulonglong2*)&S.a2t[buf][r][cg * 4];
            #pragma unroll
            for (int i = 0; i < 2; ++i) {
                ull ad = dup2(a1r[i][r]);
                sac[i][0] = fma2(ad, q.x, sac[i][0]);
                sac[i][1] = fma2(ad, q.y, sac[i][1]);
            }
        }

        // ---- normalized e: attn STG (single touch) + p STS (tf32) ----
        #pragma unroll
        for (int i = 0; i < 2; ++i) {
            const int row = rp * 2 + i;
            const int4 m = mq_buf[buf][i];
            float e0, e1, e2, e3;
            unpack2(sac[i][0], e0, e1);
            unpack2(sac[i][1], e2, e3);
            float4 e;
            e.x = m.x ? ex2(e0) : 0.f;
            e.y = m.y ? ex2(e1) : 0.f;
            e.z = m.z ? ex2(e2) : 0.f;
            e.w = m.w ? ex2(e3) : 0.f;
            *(float4*)(attnbase + (size_t)row * kL + j0 + cg * 4) = e;
            uint4 u;
            u.x = f2tf32(e.x); u.y = f2tf32(e.y);
            u.z = f2tf32(e.z); u.w = f2tf32(e.w);
            *(uint4*)&S.p[buf][row][cg * 4] = u;
        }

        // ---- mask prefetch 2 tiles ahead ----
        {
            const int jm = (jt + 2 < NTILES) ? (jt + 2) * KT : 0;
            #pragma unroll
            for (int i = 0; i < 2; ++i)
                mq_buf[buf][i] =
                    *(const int4*)(mbase + (size_t)(rp * 2 + i) * kL + jm + cg * 4);
        }

        // ---- stage next a2 tile ----
        if (t < 64)
            *(float4*)&S.a2t[buf ^ 1][ar][ac * 4] = a2n;

        cp_wait1();        // v tile jt resident
        __syncthreads();   // publish p/a2/v(jt)

        // ---- HMMA: D += E_norm * V  (V raw f32 -> tf32 truncation) ----
        const uint32_t* vt = &S.v[vcur][0][0];
        #pragma unroll
        for (int s = 0; s < 4; ++s) {
            const int k0 = 8 * s + tig;
            uint32_t a[2][4];
            #pragma unroll
            for (int mt = 0; mt < 2; ++mt) {
                const uint32_t* pr = &S.p[buf][32 * wm + 16 * mt][0];
                a[mt][0] = pr[(size_t)qid * PSTRIDE + k0];
                a[mt][1] = pr[(size_t)(qid + 8) * PSTRIDE + k0];
                a[mt][2] = pr[(size_t)qid * PSTRIDE + k0 + 4];
                a[mt][3] = pr[(size_t)(qid + 8) * PSTRIDE + k0 + 4];
            }
            #pragma unroll
            for (int nt = 0; nt < 4; ++nt) {
                const int n = 32 * wn + 8 * nt + qid;
                uint32_t b0 = vt[(size_t)(8 * s + tig) * VSTRIDE + n];
                uint32_t b1 = vt[(size_t)(8 * s + 4 + tig) * VSTRIDE + n];
                mma_tf32(acc[0][nt], a[0], b0, b1);
                mma_tf32(acc[1][nt], a[1], b0, b1);
            }
        }

        vcur = vnxt;
        vnxt = (vnxt == 2) ? 0 : vnxt + 1;
    }

    // ---- out epilogue: accumulators are already normalized ----
    #pragma unroll
    for (int mt = 0; mt < 2; ++mt) {
        const int row0 = 32 * wm + 16 * mt + qid;
        #pragma unroll
        for (int nt = 0; nt < 4; ++nt) {
            const int col = 32 * wn + 8 * nt + 2 * tig;
            float2 lo; lo.x = acc[mt][nt][0]; lo.y = acc[mt][nt][1];
            float2 hi; hi.x = acc[mt][nt][2]; hi.y = acc[mt][nt][3];
            *(float2*)(outbase + (size_t)row0 * kDV + col)       = lo;
            *(float2*)(outbase + (size_t)(row0 + 8) * kDV + col) = hi;
        }
    }
}

} // namespace

extern "C" void kernel_launch(void* const* d_in, const int* in_sizes, int n_in,
                              void* d_out, int out_size) {
    const float* v    = (const float*)d_in[0];
    const float* a1   = (const float*)d_in[1];
    const float* a2   = (const float*)d_in[2];
    const int*   mask = (const int*)d_in[3];

    float* out  = (float*)d_out;
    float* attn = out + (size_t)kB * kH * kL * kDV;

    const int smem = (int)sizeof(SmemLayout);
    cudaFuncSetAttribute(fra_kernel, cudaFuncAttributeMaxDynamicSharedMemorySize, smem);

    dim3 grid(kH, kL / TM, kB);   // heads fastest -> mask tile L2 reuse across 8 heads
    fra_kernel<<<grid, NT, smem>>>(v, a1, a2, mask, out, attn);
}